// round 1
// baseline (speedup 1.0000x reference)
#include <cuda_runtime.h>
#include <math.h>

#define B 2
#define D 768
#define H 16
#define HD 48
#define L 3
#define N_IMG 1024
#define N_PAST 16
#define T_DEC 20
#define S0 (N_IMG + 1 + N_PAST)    // 1041
#define SMAX (S0 + T_DEC)          // 1061
#define M0 (B * S0)                // 2082
#define D3 (3 * D)                 // 2304
#define DFF (4 * D)                // 3072
#define CACHE_L (B * H * SMAX * HD)

#define ATT_SCALE 0.14433756729740643f  // 1/sqrt(48)

// ------------------------- static device scratch -------------------------
__device__ float g_x[M0 * D];
__device__ float g_h[M0 * D];
__device__ float g_qkv[M0 * D3];
__device__ float g_ff[M0 * DFF];
__device__ float g_ctx[M0 * D];
__device__ float g_K[L * CACHE_L];
__device__ float g_V[L * CACHE_L];
__device__ float g_xvec[B * D];
__device__ float g_hvec[B * D];
__device__ float g_qvec[B * D];
__device__ float g_cvec[B * D];
__device__ float g_fvec[B * DFF];
__device__ float g_gvec[B * D];

// ------------------------- helpers -------------------------
__device__ __forceinline__ float gelu_exact(float x) {
    return 0.5f * x * (1.0f + erff(x * 0.7071067811865475f));
}

// ------------------------- embed -------------------------
__global__ void embed_kernel(const float* __restrict__ feats,
                             const float* __restrict__ img_pos,
                             const int* __restrict__ intent,
                             const float* __restrict__ int_emb,
                             const float* __restrict__ past,
                             const float* __restrict__ past_W,
                             const float* __restrict__ past_b,
                             const float* __restrict__ time_emb,
                             float* __restrict__ X) {
    int idx = blockIdx.x * blockDim.x + threadIdx.x;
    if (idx >= B * S0 * D) return;
    int d = idx % D;
    int s = (idx / D) % S0;
    int b = idx / (D * S0);
    float v;
    if (s < N_IMG) {
        v = feats[((size_t)b * D + d) * N_IMG + s] + img_pos[(size_t)s * D + d];
    } else if (s == N_IMG) {
        int ii = intent[b] - 1;
        ii = ii < 0 ? 0 : (ii > 2 ? 2 : ii);
        v = int_emb[ii * D + d];
    } else {
        int j = s - N_IMG - 1;
        v = past_b[d] + time_emb[j * D + d];
        #pragma unroll
        for (int c = 0; c < 6; c++)
            v += past[(b * N_PAST + j) * 6 + c] * past_W[c * D + d];
    }
    X[idx] = v;
}

// ------------------------- layernorm (one block per row) -------------------------
__global__ void ln_kernel(const float* __restrict__ X, float* __restrict__ Y,
                          const float* __restrict__ gam, const float* __restrict__ bet) {
    int row = blockIdx.x;
    const float* x = X + (size_t)row * D;
    float* y = Y + (size_t)row * D;
    __shared__ float red[256];
    int t = threadIdx.x;
    float s = 0.f;
    for (int i = t; i < D; i += 256) s += x[i];
    red[t] = s; __syncthreads();
    for (int o = 128; o > 0; o >>= 1) { if (t < o) red[t] += red[t + o]; __syncthreads(); }
    float mean = red[0] * (1.0f / D);
    __syncthreads();
    float vs = 0.f;
    for (int i = t; i < D; i += 256) { float dd = x[i] - mean; vs += dd * dd; }
    red[t] = vs; __syncthreads();
    for (int o = 128; o > 0; o >>= 1) { if (t < o) red[t] += red[t + o]; __syncthreads(); }
    float inv = rsqrtf(red[0] * (1.0f / D) + 1e-5f);
    for (int i = t; i < D; i += 256)
        y[i] = (x[i] - mean) * inv * gam[i] + bet[i];
}

// ------------------------- tiled fp32 GEMM -------------------------
// C[M,N] = act(A[M,K] @ W[K,N] + bias[N] (+ R[M,N]))
#define GBM 64
#define GBN 64
#define GBK 16
__global__ void gemm_kernel(const float* __restrict__ A, const float* __restrict__ W,
                            const float* __restrict__ bias, const float* __restrict__ R,
                            float* __restrict__ C, int M, int N, int K, int act) {
    __shared__ __align__(16) float As[GBK][GBM];
    __shared__ __align__(16) float Ws[GBK][GBN];
    int tid = threadIdx.x;
    int row0 = blockIdx.y * GBM;
    int col0 = blockIdx.x * GBN;
    int tr = (tid / 16) * 4;
    int tc = (tid % 16) * 4;
    float acc[4][4] = {};
    for (int k0 = 0; k0 < K; k0 += GBK) {
        #pragma unroll
        for (int i = tid; i < GBM * GBK; i += 256) {
            int m = i / GBK, kk = i % GBK;
            int gm = row0 + m;
            As[kk][m] = (gm < M) ? A[(size_t)gm * K + k0 + kk] : 0.f;
        }
        #pragma unroll
        for (int i = tid; i < GBK * GBN; i += 256) {
            int kk = i / GBN, n = i % GBN;
            Ws[kk][n] = W[(size_t)(k0 + kk) * N + col0 + n];
        }
        __syncthreads();
        #pragma unroll
        for (int kk = 0; kk < GBK; kk++) {
            float4 av = *reinterpret_cast<const float4*>(&As[kk][tr]);
            float4 wv = *reinterpret_cast<const float4*>(&Ws[kk][tc]);
            float a[4] = {av.x, av.y, av.z, av.w};
            float w[4] = {wv.x, wv.y, wv.z, wv.w};
            #pragma unroll
            for (int i = 0; i < 4; i++)
                #pragma unroll
                for (int j = 0; j < 4; j++)
                    acc[i][j] += a[i] * w[j];
        }
        __syncthreads();
    }
    #pragma unroll
    for (int i = 0; i < 4; i++) {
        int gm = row0 + tr + i;
        if (gm >= M) continue;
        #pragma unroll
        for (int j = 0; j < 4; j++) {
            int gn = col0 + tc + j;
            float v = acc[i][j] + bias[gn];
            if (R) v += R[(size_t)gm * N + gn];
            if (act == 1) v = fmaxf(v, 0.f);
            C[(size_t)gm * N + gn] = v;
        }
    }
}

// ------------------------- scatter prefill K,V to caches -------------------------
__global__ void scatter_kv(const float* __restrict__ qkv,
                           float* __restrict__ Kc, float* __restrict__ Vc) {
    int idx = blockIdx.x * blockDim.x + threadIdx.x;
    if (idx >= B * S0 * D) return;
    int e = idx % D;
    int s = (idx / D) % S0;
    int b = idx / (D * S0);
    int h = e / HD, ee = e % HD;
    size_t dst = (((size_t)(b * H + h)) * SMAX + s) * HD + ee;
    size_t src = ((size_t)(b * S0 + s)) * D3;
    Kc[dst] = qkv[src + D + e];
    Vc[dst] = qkv[src + 2 * D + e];
}

// ------------------------- prefill attention (flash, warp per query) -------------------------
__global__ void attn_prefill(const float* __restrict__ QKV,
                             const float* __restrict__ Kc,
                             const float* __restrict__ Vc,
                             float* __restrict__ O) {
    int bh = blockIdx.y;
    int b = bh / H, h = bh % H;
    int q0 = blockIdx.x * 4;
    int warp = threadIdx.x >> 5, lane = threadIdx.x & 31;
    int qrow = q0 + warp;
    if (qrow >= S0) qrow = S0 - 1;   // duplicate compute, no write

    __shared__ float qs[4][HD];
    __shared__ float Ks[32][HD];
    __shared__ float Vs[32][HD];

    {
        size_t qb = ((size_t)(b * S0 + qrow)) * D3 + h * HD;
        qs[warp][lane] = QKV[qb + lane];
        if (lane < 16) qs[warp][32 + lane] = QKV[qb + 32 + lane];
    }
    __syncthreads();

    int jmax_blk = q0 + 3; if (jmax_blk >= S0) jmax_blk = S0 - 1;
    size_t kvbase = (size_t)bh * SMAX * HD;

    float mrun = -INFINITY, srun = 0.f, acc0 = 0.f, acc1 = 0.f;

    for (int j0 = 0; j0 <= jmax_blk; j0 += 32) {
        for (int i = threadIdx.x; i < 32 * HD; i += 128) {
            int r = i / HD, c = i % HD;
            int j = j0 + r;
            float kv = 0.f, vv = 0.f;
            if (j < S0) {
                kv = Kc[kvbase + (size_t)j * HD + c];
                vv = Vc[kvbase + (size_t)j * HD + c];
            }
            Ks[r][c] = kv; Vs[r][c] = vv;
        }
        __syncthreads();

        int j = j0 + lane;
        float s = -INFINITY;
        if (j <= qrow) {
            s = 0.f;
            #pragma unroll
            for (int d = 0; d < HD; d++) s += qs[warp][d] * Ks[lane][d];
            s *= ATT_SCALE;
        }
        float cm = s;
        #pragma unroll
        for (int o = 16; o > 0; o >>= 1) cm = fmaxf(cm, __shfl_xor_sync(0xffffffffu, cm, o));
        float mnew = fmaxf(mrun, cm);
        float corr = expf(mrun - mnew);
        float p = (j <= qrow) ? expf(s - mnew) : 0.f;
        float ps = p;
        #pragma unroll
        for (int o = 16; o > 0; o >>= 1) ps += __shfl_xor_sync(0xffffffffu, ps, o);
        srun = srun * corr + ps;
        mrun = mnew;
        acc0 *= corr; acc1 *= corr;
        #pragma unroll 4
        for (int src = 0; src < 32; src++) {
            float pp = __shfl_sync(0xffffffffu, p, src);
            acc0 += pp * Vs[src][lane];
            if (lane < 16) acc1 += pp * Vs[src][32 + lane];
        }
        __syncthreads();
    }

    if (q0 + warp < S0) {
        float inv = 1.f / srun;
        size_t ob = ((size_t)(b * S0 + qrow)) * D + h * HD;
        O[ob + lane] = acc0 * inv;
        if (lane < 16) O[ob + 32 + lane] = acc1 * inv;
    }
}

// ------------------------- copy last prefill row -------------------------
__global__ void copy_last(const float* __restrict__ X, float* __restrict__ xv) {
    int idx = blockIdx.x * blockDim.x + threadIdx.x;
    if (idx >= B * D) return;
    int b = idx / D, d = idx % D;
    xv[idx] = X[((size_t)(b * S0 + S0 - 1)) * D + d];
}

// ------------------------- decode GEMV (M=2 hardcoded) -------------------------
// C[m,n] = act(A[m,:] @ W[:,n] + bias[n] (+ R[m,n]))
__global__ void gemv_kernel(const float* __restrict__ A, const float* __restrict__ W,
                            const float* __restrict__ bias, const float* __restrict__ R,
                            float* __restrict__ C, int N, int K, int act) {
    __shared__ float As[2 * DFF];
    int t = threadIdx.x;
    for (int i = t; i < 2 * K; i += 256) As[i] = A[i];
    __syncthreads();
    int n = blockIdx.x * 256 + t;
    float a0 = 0.f, a1 = 0.f;
    #pragma unroll 8
    for (int k = 0; k < K; k++) {
        float w = W[(size_t)k * N + n];
        a0 += As[k] * w;
        a1 += As[K + k] * w;
    }
    a0 += bias[n]; a1 += bias[n];
    if (R) { a0 += R[n]; a1 += R[N + n]; }
    if (act == 1) { a0 = fmaxf(a0, 0.f); a1 = fmaxf(a1, 0.f); }
    else if (act == 2) { a0 = gelu_exact(a0); a1 = gelu_exact(a1); }
    C[n] = a0; C[N + n] = a1;
}

// ------------------------- decode qkv GEMV with KV-cache scatter -------------------------
__global__ void qkv_dec_kernel(const float* __restrict__ A, const float* __restrict__ W,
                               const float* __restrict__ bias,
                               float* __restrict__ qv, float* __restrict__ Kc,
                               float* __restrict__ Vc, int s_new) {
    __shared__ float As[2 * D];
    int t = threadIdx.x;
    for (int i = t; i < 2 * D; i += 256) As[i] = A[i];
    __syncthreads();
    int n = blockIdx.x * 256 + t;
    float a0 = 0.f, a1 = 0.f;
    #pragma unroll 8
    for (int k = 0; k < D; k++) {
        float w = W[(size_t)k * D3 + n];
        a0 += As[k] * w;
        a1 += As[D + k] * w;
    }
    a0 += bias[n]; a1 += bias[n];
    if (n < D) {
        qv[n] = a0; qv[D + n] = a1;
    } else if (n < 2 * D) {
        int e = n - D; int h = e / HD, ee = e % HD;
        Kc[(((size_t)(0 * H + h)) * SMAX + s_new) * HD + ee] = a0;
        Kc[(((size_t)(1 * H + h)) * SMAX + s_new) * HD + ee] = a1;
    } else {
        int e = n - 2 * D; int h = e / HD, ee = e % HD;
        Vc[(((size_t)(0 * H + h)) * SMAX + s_new) * HD + ee] = a0;
        Vc[(((size_t)(1 * H + h)) * SMAX + s_new) * HD + ee] = a1;
    }
}

// ------------------------- decode attention (block per b,h) -------------------------
__global__ void attn_dec(const float* __restrict__ qv, const float* __restrict__ Kc,
                         const float* __restrict__ Vc, float* __restrict__ cv, int Slen) {
    int bh = blockIdx.x;
    int b = bh / H, h = bh % H;
    __shared__ float qs[HD];
    __shared__ float sc[SMAX];
    __shared__ float red[256];
    int t = threadIdx.x;
    if (t < HD) qs[t] = qv[b * D + h * HD + t];
    __syncthreads();
    size_t base = (size_t)bh * SMAX * HD;
    float lmax = -INFINITY;
    for (int j = t; j < Slen; j += 256) {
        float s = 0.f;
        #pragma unroll
        for (int d = 0; d < HD; d++) s += qs[d] * Kc[base + (size_t)j * HD + d];
        s *= ATT_SCALE;
        sc[j] = s;
        lmax = fmaxf(lmax, s);
    }
    red[t] = lmax; __syncthreads();
    for (int o = 128; o > 0; o >>= 1) { if (t < o) red[t] = fmaxf(red[t], red[t + o]); __syncthreads(); }
    float m = red[0];
    __syncthreads();
    float ls = 0.f;
    for (int j = t; j < Slen; j += 256) {
        float p = expf(sc[j] - m);
        sc[j] = p;
        ls += p;
    }
    red[t] = ls; __syncthreads();
    for (int o = 128; o > 0; o >>= 1) { if (t < o) red[t] += red[t + o]; __syncthreads(); }
    float inv = 1.f / red[0];
    __syncthreads();
    for (int d = t; d < HD; d += 256) {
        float a = 0.f;
        for (int j = 0; j < Slen; j++) a += sc[j] * Vc[base + (size_t)j * HD + d];
        cv[b * D + h * HD + d] = a * inv;
    }
}

// ------------------------- decode head stage 2 + next-token embed -------------------------
__global__ void head2_kernel(const float* __restrict__ gvec,
                             const float* __restrict__ dec2_W, const float* __restrict__ dec2_b,
                             const float* __restrict__ pos_W, const float* __restrict__ pos_b,
                             const float* __restrict__ time_emb, int t_step,
                             float* __restrict__ out, float* __restrict__ xv) {
    int b = blockIdx.x;
    __shared__ float r0[256], r1[256];
    int tid = threadIdx.x;
    float p0 = 0.f, p1 = 0.f;
    for (int k = tid; k < D; k += 256) {
        float g = gvec[b * D + k];
        p0 += g * dec2_W[k * 2];
        p1 += g * dec2_W[k * 2 + 1];
    }
    r0[tid] = p0; r1[tid] = p1; __syncthreads();
    for (int o = 128; o > 0; o >>= 1) {
        if (tid < o) { r0[tid] += r0[tid + o]; r1[tid] += r1[tid + o]; }
        __syncthreads();
    }
    p0 = r0[0] + dec2_b[0];
    p1 = r1[0] + dec2_b[1];
    if (tid == 0) {
        out[(b * T_DEC + t_step) * 2]     = p0;
        out[(b * T_DEC + t_step) * 2 + 1] = p1;
    }
    for (int d = tid; d < D; d += 256)
        xv[b * D + d] = p0 * pos_W[d] + p1 * pos_W[D + d] + pos_b[d]
                        + time_emb[(N_PAST + t_step) * D + d];
}

// ------------------------- host orchestration -------------------------
extern "C" void kernel_launch(void* const* d_in, const int* in_sizes, int n_in,
                              void* d_out, int out_size) {
    const float* feats    = (const float*)d_in[0];
    const float* past     = (const float*)d_in[1];
    const int*   intent   = (const int*)  d_in[2];
    const float* img_pos  = (const float*)d_in[3];
    const float* time_emb = (const float*)d_in[4];
    const float* int_emb  = (const float*)d_in[5];
    const float* past_W   = (const float*)d_in[6];
    const float* past_b   = (const float*)d_in[7];
    const float* pos_W    = (const float*)d_in[8];
    const float* pos_b    = (const float*)d_in[9];
    const float* ln1_g    = (const float*)d_in[10];
    const float* ln1_b    = (const float*)d_in[11];
    const float* qkv_W    = (const float*)d_in[12];
    const float* qkv_b    = (const float*)d_in[13];
    const float* out_W    = (const float*)d_in[14];
    const float* out_b    = (const float*)d_in[15];
    const float* ln2_g    = (const float*)d_in[16];
    const float* ln2_b    = (const float*)d_in[17];
    const float* ff1_W    = (const float*)d_in[18];
    const float* ff1_b    = (const float*)d_in[19];
    const float* ff2_W    = (const float*)d_in[20];
    const float* ff2_b    = (const float*)d_in[21];
    const float* dec1_W   = (const float*)d_in[22];
    const float* dec1_b   = (const float*)d_in[23];
    const float* dec2_W   = (const float*)d_in[24];
    const float* dec2_b   = (const float*)d_in[25];
    float* out = (float*)d_out;

    float *px, *ph, *pqkv, *pff, *pctx, *pK, *pV, *pxv, *phv, *pqv, *pcv, *pfv, *pgv;
    cudaGetSymbolAddress((void**)&px,   g_x);
    cudaGetSymbolAddress((void**)&ph,   g_h);
    cudaGetSymbolAddress((void**)&pqkv, g_qkv);
    cudaGetSymbolAddress((void**)&pff,  g_ff);
    cudaGetSymbolAddress((void**)&pctx, g_ctx);
    cudaGetSymbolAddress((void**)&pK,   g_K);
    cudaGetSymbolAddress((void**)&pV,   g_V);
    cudaGetSymbolAddress((void**)&pxv,  g_xvec);
    cudaGetSymbolAddress((void**)&phv,  g_hvec);
    cudaGetSymbolAddress((void**)&pqv,  g_qvec);
    cudaGetSymbolAddress((void**)&pcv,  g_cvec);
    cudaGetSymbolAddress((void**)&pfv,  g_fvec);
    cudaGetSymbolAddress((void**)&pgv,  g_gvec);

    // ---- embed ----
    {
        int n = B * S0 * D;
        embed_kernel<<<(n + 255) / 256, 256>>>(feats, img_pos, intent, int_emb,
                                               past, past_W, past_b, time_emb, px);
    }

    // ---- prefill: 3 layers ----
    for (int l = 0; l < L; l++) {
        const float* KcL = pK + (size_t)l * CACHE_L;
        const float* VcL = pV + (size_t)l * CACHE_L;
        float* KcLm = pK + (size_t)l * CACHE_L;
        float* VcLm = pV + (size_t)l * CACHE_L;

        ln_kernel<<<M0, 256>>>(px, ph, ln1_g + l * D, ln1_b + l * D);
        gemm_kernel<<<dim3(D3 / GBN, (M0 + GBM - 1) / GBM), 256>>>(
            ph, qkv_W + (size_t)l * D * D3, qkv_b + l * D3, nullptr, pqkv, M0, D3, D, 0);
        {
            int n = B * S0 * D;
            scatter_kv<<<(n + 255) / 256, 256>>>(pqkv, KcLm, VcLm);
        }
        attn_prefill<<<dim3((S0 + 3) / 4, B * H), 128>>>(pqkv, KcL, VcL, pctx);
        gemm_kernel<<<dim3(D / GBN, (M0 + GBM - 1) / GBM), 256>>>(
            pctx, out_W + (size_t)l * D * D, out_b + l * D, px, px, M0, D, D, 0);
        ln_kernel<<<M0, 256>>>(px, ph, ln2_g + l * D, ln2_b + l * D);
        gemm_kernel<<<dim3(DFF / GBN, (M0 + GBM - 1) / GBM), 256>>>(
            ph, ff1_W + (size_t)l * D * DFF, ff1_b + l * DFF, nullptr, pff, M0, DFF, D, 1);
        gemm_kernel<<<dim3(D / GBN, (M0 + GBM - 1) / GBM), 256>>>(
            pff, ff2_W + (size_t)l * DFF * D, ff2_b + l * D, px, px, M0, D, DFF, 0);
    }

    copy_last<<<(B * D + 255) / 256, 256>>>(px, pxv);

    // ---- autoregressive decode: 20 steps ----
    for (int t = 0; t < T_DEC; t++) {
        // head: p = gelu(xlast @ dec1 + b) @ dec2 + b ; also build next token into xvec
        gemv_kernel<<<D / 256, 256>>>(pxv, dec1_W, dec1_b, nullptr, pgv, D, D, 2);
        head2_kernel<<<B, 256>>>(pgv, dec2_W, dec2_b, pos_W, pos_b, time_emb, t, out, pxv);

        int s_new = S0 + t;
        for (int l = 0; l < L; l++) {
            float* KcL = pK + (size_t)l * CACHE_L;
            float* VcL = pV + (size_t)l * CACHE_L;

            ln_kernel<<<B, 256>>>(pxv, phv, ln1_g + l * D, ln1_b + l * D);
            qkv_dec_kernel<<<D3 / 256, 256>>>(phv, qkv_W + (size_t)l * D * D3,
                                              qkv_b + l * D3, pqv, KcL, VcL, s_new);
            attn_dec<<<B * H, 256>>>(pqv, KcL, VcL, pcv, s_new + 1);
            gemv_kernel<<<D / 256, 256>>>(pcv, out_W + (size_t)l * D * D,
                                          out_b + l * D, pxv, pxv, D, D, 0);
            ln_kernel<<<B, 256>>>(pxv, phv, ln2_g + l * D, ln2_b + l * D);
            gemv_kernel<<<DFF / 256, 256>>>(phv, ff1_W + (size_t)l * D * DFF,
                                            ff1_b + l * DFF, nullptr, pfv, DFF, D, 1);
            gemv_kernel<<<D / 256, 256>>>(pfv, ff2_W + (size_t)l * DFF * D,
                                          ff2_b + l * D, pxv, pxv, D, DFF, 0);
        }
    }
}

// round 2
// speedup vs baseline: 6.9752x; 6.9752x over previous
#include <cuda_runtime.h>
#include <math.h>

#define B 2
#define D 768
#define H 16
#define HD 48
#define L 3
#define N_IMG 1024
#define N_PAST 16
#define T_DEC 20
#define S0 (N_IMG + 1 + N_PAST)    // 1041
#define SMAX (S0 + T_DEC)          // 1061
#define M0 (B * S0)                // 2082
#define D3 (3 * D)                 // 2304
#define DFF (4 * D)                // 3072
#define CACHE_L (B * H * SMAX * HD)
#define NSPLIT 4

#define ATT_SCALE 0.14433756729740643f  // 1/sqrt(48)

// ------------------------- static device scratch -------------------------
__device__ float g_x[M0 * D];
__device__ float g_h[M0 * D];
__device__ float g_qkv[M0 * D3];
__device__ float g_ff[M0 * DFF];
__device__ float g_ctx[M0 * D];
__device__ float g_K[L * CACHE_L];
__device__ float g_V[L * CACHE_L];
__device__ float g_xvec[B * D];
__device__ float g_qvec[B * D];
__device__ float g_fvec[B * DFF];
__device__ float g_gvec[B * D];
__device__ float g_part[8 * 2 * DFF];          // split-K partials (max 49152)
__device__ float g_attA[B * H * NSPLIT * HD];  // unnormalized PV partials
__device__ float g_attM[B * H * NSPLIT];       // local max
__device__ float g_attL[B * H * NSPLIT];       // local sum

__device__ __forceinline__ float gelu_exact(float x) {
    return 0.5f * x * (1.0f + erff(x * 0.7071067811865475f));
}

// ------------------------- embed -------------------------
__global__ void embed_kernel(const float* __restrict__ feats,
                             const float* __restrict__ img_pos,
                             const int* __restrict__ intent,
                             const float* __restrict__ int_emb,
                             const float* __restrict__ past,
                             const float* __restrict__ past_W,
                             const float* __restrict__ past_b,
                             const float* __restrict__ time_emb,
                             float* __restrict__ X) {
    int idx = blockIdx.x * blockDim.x + threadIdx.x;
    if (idx >= B * S0 * D) return;
    int d = idx % D;
    int s = (idx / D) % S0;
    int b = idx / (D * S0);
    float v;
    if (s < N_IMG) {
        v = feats[((size_t)b * D + d) * N_IMG + s] + img_pos[(size_t)s * D + d];
    } else if (s == N_IMG) {
        int ii = intent[b] - 1;
        ii = ii < 0 ? 0 : (ii > 2 ? 2 : ii);
        v = int_emb[ii * D + d];
    } else {
        int j = s - N_IMG - 1;
        v = past_b[d] + time_emb[j * D + d];
        #pragma unroll
        for (int c = 0; c < 6; c++)
            v += past[(b * N_PAST + j) * 6 + c] * past_W[c * D + d];
    }
    X[idx] = v;
}

// ------------------------- layernorm (prefill; one block per row) -------------------------
__global__ void ln_kernel(const float* __restrict__ X, float* __restrict__ Y,
                          const float* __restrict__ gam, const float* __restrict__ bet) {
    int row = blockIdx.x;
    const float* x = X + (size_t)row * D;
    float* y = Y + (size_t)row * D;
    __shared__ float red[256];
    int t = threadIdx.x;
    float s = 0.f;
    for (int i = t; i < D; i += 256) s += x[i];
    red[t] = s; __syncthreads();
    for (int o = 128; o > 0; o >>= 1) { if (t < o) red[t] += red[t + o]; __syncthreads(); }
    float mean = red[0] * (1.0f / D);
    __syncthreads();
    float vs = 0.f;
    for (int i = t; i < D; i += 256) { float dd = x[i] - mean; vs += dd * dd; }
    red[t] = vs; __syncthreads();
    for (int o = 128; o > 0; o >>= 1) { if (t < o) red[t] += red[t + o]; __syncthreads(); }
    float inv = rsqrtf(red[0] * (1.0f / D) + 1e-5f);
    for (int i = t; i < D; i += 256)
        y[i] = (x[i] - mean) * inv * gam[i] + bet[i];
}

// ------------------------- 128x128x16 fp32 GEMM, 8x8 per thread -------------------------
#define TM 128
#define TN 128
#define TK 16
__global__ void __launch_bounds__(256, 2)
gemm_kernel(const float* __restrict__ A, const float* __restrict__ W,
            const float* __restrict__ bias, const float* __restrict__ R,
            float* __restrict__ C, int M, int N, int K, int act) {
    __shared__ float As[TK][TM];
    __shared__ float Ws[TK][TN];
    int tid = threadIdx.x;
    int warp = tid >> 5, lane = tid & 31;
    int wm = warp & 1, wn = warp >> 1;          // warps 2(M) x 4(N)
    int lm = lane & 7, ln = lane >> 3;          // lanes 8(M) x 4(N)
    int tr = (wm * 8 + lm) * 8;                 // 0..120
    int tc = (wn * 4 + ln) * 8;                 // 0..120
    int row0 = blockIdx.y * TM, col0 = blockIdx.x * TN;
    float acc[8][8] = {};

    for (int k0 = 0; k0 < K; k0 += TK) {
        // A tile 128x16: 512 float4, 2/thread (32B contiguous per thread)
        #pragma unroll
        for (int i = 0; i < 2; i++) {
            int idx = tid * 2 + i;
            int r = idx >> 2, c4 = idx & 3;
            int gm = row0 + r;
            float4 v = make_float4(0.f, 0.f, 0.f, 0.f);
            if (gm < M) v = *reinterpret_cast<const float4*>(&A[(size_t)gm * K + k0 + c4 * 4]);
            As[c4 * 4 + 0][r] = v.x;
            As[c4 * 4 + 1][r] = v.y;
            As[c4 * 4 + 2][r] = v.z;
            As[c4 * 4 + 3][r] = v.w;
        }
        // W tile 16x128: coalesced
        #pragma unroll
        for (int i = 0; i < 2; i++) {
            int idx = tid * 2 + i;
            int kk = idx >> 5, c4 = idx & 31;
            *reinterpret_cast<float4*>(&Ws[kk][c4 * 4]) =
                *reinterpret_cast<const float4*>(&W[(size_t)(k0 + kk) * N + col0 + c4 * 4]);
        }
        __syncthreads();
        #pragma unroll
        for (int kk = 0; kk < TK; kk++) {
            float a[8], w[8];
            *reinterpret_cast<float4*>(a)     = *reinterpret_cast<const float4*>(&As[kk][tr]);
            *reinterpret_cast<float4*>(a + 4) = *reinterpret_cast<const float4*>(&As[kk][tr + 4]);
            *reinterpret_cast<float4*>(w)     = *reinterpret_cast<const float4*>(&Ws[kk][tc]);
            *reinterpret_cast<float4*>(w + 4) = *reinterpret_cast<const float4*>(&Ws[kk][tc + 4]);
            #pragma unroll
            for (int i = 0; i < 8; i++)
                #pragma unroll
                for (int j = 0; j < 8; j++)
                    acc[i][j] += a[i] * w[j];
        }
        __syncthreads();
    }

    #pragma unroll
    for (int i = 0; i < 8; i++) {
        int gm = row0 + tr + i;
        if (gm >= M) continue;
        #pragma unroll
        for (int jc = 0; jc < 2; jc++) {
            int gn = col0 + tc + jc * 4;
            float4 bv = *reinterpret_cast<const float4*>(&bias[gn]);
            float4 v;
            v.x = acc[i][jc * 4 + 0] + bv.x;
            v.y = acc[i][jc * 4 + 1] + bv.y;
            v.z = acc[i][jc * 4 + 2] + bv.z;
            v.w = acc[i][jc * 4 + 3] + bv.w;
            if (R) {
                float4 rv = *reinterpret_cast<const float4*>(&R[(size_t)gm * N + gn]);
                v.x += rv.x; v.y += rv.y; v.z += rv.z; v.w += rv.w;
            }
            if (act == 1) {
                v.x = fmaxf(v.x, 0.f); v.y = fmaxf(v.y, 0.f);
                v.z = fmaxf(v.z, 0.f); v.w = fmaxf(v.w, 0.f);
            }
            *reinterpret_cast<float4*>(&C[(size_t)gm * N + gn]) = v;
        }
    }
}

// ------------------------- scatter prefill K,V to caches -------------------------
__global__ void scatter_kv(const float* __restrict__ qkv,
                           float* __restrict__ Kc, float* __restrict__ Vc) {
    int idx = blockIdx.x * blockDim.x + threadIdx.x;
    if (idx >= B * S0 * D) return;
    int e = idx % D;
    int s = (idx / D) % S0;
    int b = idx / (D * S0);
    int h = e / HD, ee = e % HD;
    size_t dst = (((size_t)(b * H + h)) * SMAX + s) * HD + ee;
    size_t src = ((size_t)(b * S0 + s)) * D3;
    Kc[dst] = qkv[src + D + e];
    Vc[dst] = qkv[src + 2 * D + e];
}

// ------------------------- prefill attention (flash, warp per query) -------------------------
__global__ void attn_prefill(const float* __restrict__ QKV,
                             const float* __restrict__ Kc,
                             const float* __restrict__ Vc,
                             float* __restrict__ O) {
    int bh = blockIdx.y;
    int b = bh / H, h = bh % H;
    int q0 = blockIdx.x * 4;
    int warp = threadIdx.x >> 5, lane = threadIdx.x & 31;
    int qrow = q0 + warp;
    if (qrow >= S0) qrow = S0 - 1;

    __shared__ float qs[4][HD];
    __shared__ float Ks[32][49];  // padded: conflict-free
    __shared__ float Vs[32][49];

    {
        size_t qb = ((size_t)(b * S0 + qrow)) * D3 + h * HD;
        qs[warp][lane] = QKV[qb + lane];
        if (lane < 16) qs[warp][32 + lane] = QKV[qb + 32 + lane];
    }
    __syncthreads();

    int jmax_blk = q0 + 3; if (jmax_blk >= S0) jmax_blk = S0 - 1;
    size_t kvbase = (size_t)bh * SMAX * HD;

    float mrun = -INFINITY, srun = 0.f, acc0 = 0.f, acc1 = 0.f;

    for (int j0 = 0; j0 <= jmax_blk; j0 += 32) {
        for (int i = threadIdx.x; i < 32 * HD; i += 128) {
            int r = i / HD, c = i % HD;
            int j = j0 + r;
            float kv = 0.f, vv = 0.f;
            if (j < S0) {
                kv = Kc[kvbase + (size_t)j * HD + c];
                vv = Vc[kvbase + (size_t)j * HD + c];
            }
            Ks[r][c] = kv; Vs[r][c] = vv;
        }
        __syncthreads();

        int j = j0 + lane;
        float s = -INFINITY;
        if (j <= qrow) {
            s = 0.f;
            #pragma unroll
            for (int d = 0; d < HD; d++) s += qs[warp][d] * Ks[lane][d];
            s *= ATT_SCALE;
        }
        float cm = s;
        #pragma unroll
        for (int o = 16; o > 0; o >>= 1) cm = fmaxf(cm, __shfl_xor_sync(0xffffffffu, cm, o));
        float mnew = fmaxf(mrun, cm);
        float corr = expf(mrun - mnew);
        float p = (j <= qrow) ? expf(s - mnew) : 0.f;
        float ps = p;
        #pragma unroll
        for (int o = 16; o > 0; o >>= 1) ps += __shfl_xor_sync(0xffffffffu, ps, o);
        srun = srun * corr + ps;
        mrun = mnew;
        acc0 *= corr; acc1 *= corr;
        #pragma unroll 4
        for (int src = 0; src < 32; src++) {
            float pp = __shfl_sync(0xffffffffu, p, src);
            acc0 += pp * Vs[src][lane];
            if (lane < 16) acc1 += pp * Vs[src][32 + lane];
        }
        __syncthreads();
    }

    if (q0 + warp < S0) {
        float inv = 1.f / srun;
        size_t ob = ((size_t)(b * S0 + qrow)) * D + h * HD;
        O[ob + lane] = acc0 * inv;
        if (lane < 16) O[ob + 32 + lane] = acc1 * inv;
    }
}

// ------------------------- copy last prefill row -------------------------
__global__ void copy_last(const float* __restrict__ X, float* __restrict__ xv) {
    int idx = blockIdx.x * blockDim.x + threadIdx.x;
    if (idx >= B * D) return;
    int b = idx / D, d = idx % D;
    xv[idx] = X[((size_t)(b * S0 + S0 - 1)) * D + d];
}

// ===================== decode: split-K GEMV, two stage =====================
// A-prep modes
#define AP_PLAIN 0
#define AP_LN    1
#define AP_ATT   2

// stage 1: partial[m][n] over k-range [blockIdx.y*len, +len)
__global__ void __launch_bounds__(256)
gemv_part(const float* __restrict__ Avec, const float* __restrict__ W,
          float* __restrict__ part, int N, int K, int KS, int mode,
          const float* __restrict__ gam, const float* __restrict__ bet,
          const float* __restrict__ attA, const float* __restrict__ attM,
          const float* __restrict__ attL) {
    __shared__ float Asl[2][192];
    __shared__ float red[256], red2[256];
    int t = threadIdx.x;
    int len = K / KS;
    int k0 = blockIdx.y * len;

    if (mode == AP_PLAIN) {
        for (int i = t; i < 2 * len; i += 256) {
            int m = i / len, kk = i % len;
            Asl[m][kk] = Avec[m * K + k0 + kk];
        }
    } else if (mode == AP_LN) {
        float mean[2], inv[2];
        #pragma unroll
        for (int m = 0; m < 2; m++) {
            float s = 0.f, ss = 0.f;
            for (int i = t; i < K; i += 256) {
                float v = Avec[m * K + i];
                s += v; ss += v * v;
            }
            red[t] = s; red2[t] = ss; __syncthreads();
            for (int o = 128; o > 0; o >>= 1) {
                if (t < o) { red[t] += red[t + o]; red2[t] += red2[t + o]; }
                __syncthreads();
            }
            mean[m] = red[0] * (1.0f / D);
            inv[m] = rsqrtf(red2[0] * (1.0f / D) - mean[m] * mean[m] + 1e-5f);
            __syncthreads();
        }
        for (int i = t; i < 2 * len; i += 256) {
            int m = i / len, kk = i % len;
            int gk = k0 + kk;
            Asl[m][kk] = (Avec[m * K + gk] - mean[m]) * inv[m] * gam[gk] + bet[gk];
        }
    } else { // AP_ATT: combine NSPLIT flash partials
        for (int i = t; i < 2 * len; i += 256) {
            int m = i / len, e = k0 + i % len;
            int h = e / HD, d = e % HD;
            int bh = m * H + h;
            float M = -INFINITY;
            #pragma unroll
            for (int s = 0; s < NSPLIT; s++) M = fmaxf(M, attM[bh * NSPLIT + s]);
            float num = 0.f, den = 0.f;
            #pragma unroll
            for (int s = 0; s < NSPLIT; s++) {
                float w = expf(attM[bh * NSPLIT + s] - M);
                num += w * attA[(bh * NSPLIT + s) * HD + d];
                den += w * attL[bh * NSPLIT + s];
            }
            Asl[m][i % len] = num / den;
        }
    }
    __syncthreads();

    int n = blockIdx.x * 256 + t;
    const float* Wp = W + (size_t)k0 * N + n;
    float a0 = 0.f, a1 = 0.f;
    #pragma unroll 8
    for (int kk = 0; kk < len; kk++) {
        float w = *Wp; Wp += N;
        a0 += Asl[0][kk] * w;
        a1 += Asl[1][kk] * w;
    }
    part[(blockIdx.y * 2 + 0) * N + n] = a0;
    part[(blockIdx.y * 2 + 1) * N + n] = a1;
}

// stage 2: reduce partials + bias + residual + activation + optional qkv scatter
// act: 0 none, 1 relu, 2 gelu.  scatter: 0 -> dst rows, 1 -> qkv split
__global__ void __launch_bounds__(256)
gemv_fin(const float* __restrict__ part, const float* __restrict__ bias,
         const float* __restrict__ Res, float* __restrict__ dst,
         int N, int KS, int act, int scatter, int s_new,
         float* __restrict__ Kc, float* __restrict__ Vc, float* __restrict__ qv) {
    int n = blockIdx.x * 256 + threadIdx.x;
    float a0 = bias[n], a1 = a0;
    for (int ks = 0; ks < KS; ks++) {
        a0 += part[(ks * 2 + 0) * N + n];
        a1 += part[(ks * 2 + 1) * N + n];
    }
    if (Res) { a0 += Res[n]; a1 += Res[N + n]; }
    if (act == 1) { a0 = fmaxf(a0, 0.f); a1 = fmaxf(a1, 0.f); }
    else if (act == 2) { a0 = gelu_exact(a0); a1 = gelu_exact(a1); }
    if (scatter == 0) {
        dst[n] = a0; dst[N + n] = a1;
    } else {
        if (n < D) {
            qv[n] = a0; qv[D + n] = a1;
        } else if (n < 2 * D) {
            int e = n - D; int h = e / HD, ee = e % HD;
            Kc[(((size_t)h) * SMAX + s_new) * HD + ee] = a0;
            Kc[(((size_t)(H + h)) * SMAX + s_new) * HD + ee] = a1;
        } else {
            int e = n - 2 * D; int h = e / HD, ee = e % HD;
            Vc[(((size_t)h) * SMAX + s_new) * HD + ee] = a0;
            Vc[(((size_t)(H + h)) * SMAX + s_new) * HD + ee] = a1;
        }
    }
}

// ------------------------- decode attention, split over j -------------------------
__global__ void __launch_bounds__(256)
attn_dec(const float* __restrict__ qv, const float* __restrict__ Kc,
         const float* __restrict__ Vc, int Slen,
         float* __restrict__ attA, float* __restrict__ attM, float* __restrict__ attL) {
    int bh = blockIdx.x;
    int split = blockIdx.y;
    int b = bh / H, h = bh % H;
    int len = (Slen + NSPLIT - 1) / NSPLIT;
    int j0 = split * len;
    int j1 = min(j0 + len, Slen);
    int cnt = j1 - j0;

    __shared__ float qs[HD];
    __shared__ float sc[272];
    __shared__ float red[256];
    __shared__ float red2[5 * HD];
    int t = threadIdx.x;
    if (t < HD) qs[t] = qv[b * D + h * HD + t];
    __syncthreads();

    size_t base = (size_t)bh * SMAX * HD;
    float lmax = -INFINITY;
    for (int jl = t; jl < cnt; jl += 256) {
        const float* kp = Kc + base + (size_t)(j0 + jl) * HD;
        float s = 0.f;
        #pragma unroll
        for (int d = 0; d < HD; d++) s += qs[d] * kp[d];
        s *= ATT_SCALE;
        sc[jl] = s;
        lmax = fmaxf(lmax, s);
    }
    red[t] = lmax; __syncthreads();
    for (int o = 128; o > 0; o >>= 1) { if (t < o) red[t] = fmaxf(red[t], red[t + o]); __syncthreads(); }
    float m = red[0];
    __syncthreads();
    float ls = 0.f;
    for (int jl = t; jl < cnt; jl += 256) {
        float p = expf(sc[jl] - m);
        sc[jl] = p;
        ls += p;
    }
    red[t] = ls; __syncthreads();
    for (int o = 128; o > 0; o >>= 1) { if (t < o) red[t] += red[t + o]; __syncthreads(); }
    float l = red[0];
    __syncthreads();

    // PV: 240 threads = 48 d x 5 j-groups
    if (t < 5 * HD) {
        int d = t % HD, g = t / HD;
        float a = 0.f;
        for (int jl = g; jl < cnt; jl += 5)
            a += sc[jl] * Vc[base + (size_t)(j0 + jl) * HD + d];
        red2[g * HD + d] = a;
    }
    __syncthreads();
    if (t < HD) {
        float a = red2[t] + red2[HD + t] + red2[2 * HD + t] + red2[3 * HD + t] + red2[4 * HD + t];
        attA[(bh * NSPLIT + split) * HD + t] = a;
        if (t == 0) { attM[bh * NSPLIT + split] = m; attL[bh * NSPLIT + split] = l; }
    }
}

// ------------------------- decode head stage 2 + next-token embed -------------------------
__global__ void head2_kernel(const float* __restrict__ gvec,
                             const float* __restrict__ dec2_W, const float* __restrict__ dec2_b,
                             const float* __restrict__ pos_W, const float* __restrict__ pos_b,
                             const float* __restrict__ time_emb, int t_step,
                             float* __restrict__ out, float* __restrict__ xv) {
    int b = blockIdx.x;
    __shared__ float r0[256], r1[256];
    int tid = threadIdx.x;
    float p0 = 0.f, p1 = 0.f;
    for (int k = tid; k < D; k += 256) {
        float g = gvec[b * D + k];
        p0 += g * dec2_W[k * 2];
        p1 += g * dec2_W[k * 2 + 1];
    }
    r0[tid] = p0; r1[tid] = p1; __syncthreads();
    for (int o = 128; o > 0; o >>= 1) {
        if (tid < o) { r0[tid] += r0[tid + o]; r1[tid] += r1[tid + o]; }
        __syncthreads();
    }
    p0 = r0[0] + dec2_b[0];
    p1 = r1[0] + dec2_b[1];
    if (tid == 0) {
        out[(b * T_DEC + t_step) * 2]     = p0;
        out[(b * T_DEC + t_step) * 2 + 1] = p1;
    }
    for (int d = tid; d < D; d += 256)
        xv[b * D + d] = p0 * pos_W[d] + p1 * pos_W[D + d] + pos_b[d]
                        + time_emb[(N_PAST + t_step) * D + d];
}

// ------------------------- host orchestration -------------------------
extern "C" void kernel_launch(void* const* d_in, const int* in_sizes, int n_in,
                              void* d_out, int out_size) {
    const float* feats    = (const float*)d_in[0];
    const float* past     = (const float*)d_in[1];
    const int*   intent   = (const int*)  d_in[2];
    const float* img_pos  = (const float*)d_in[3];
    const float* time_emb = (const float*)d_in[4];
    const float* int_emb  = (const float*)d_in[5];
    const float* past_W   = (const float*)d_in[6];
    const float* past_b   = (const float*)d_in[7];
    const float* pos_W    = (const float*)d_in[8];
    const float* pos_b    = (const float*)d_in[9];
    const float* ln1_g    = (const float*)d_in[10];
    const float* ln1_b    = (const float*)d_in[11];
    const float* qkv_W    = (const float*)d_in[12];
    const float* qkv_b    = (const float*)d_in[13];
    const float* out_W    = (const float*)d_in[14];
    const float* out_b    = (const float*)d_in[15];
    const float* ln2_g    = (const float*)d_in[16];
    const float* ln2_b    = (const float*)d_in[17];
    const float* ff1_W    = (const float*)d_in[18];
    const float* ff1_b    = (const float*)d_in[19];
    const float* ff2_W    = (const float*)d_in[20];
    const float* ff2_b    = (const float*)d_in[21];
    const float* dec1_W   = (const float*)d_in[22];
    const float* dec1_b   = (const float*)d_in[23];
    const float* dec2_W   = (const float*)d_in[24];
    const float* dec2_b   = (const float*)d_in[25];
    float* out = (float*)d_out;

    float *px, *ph, *pqkv, *pff, *pctx, *pK, *pV, *pxv, *pqv, *pfv, *pgv;
    float *ppart, *pattA, *pattM, *pattL;
    cudaGetSymbolAddress((void**)&px,    g_x);
    cudaGetSymbolAddress((void**)&ph,    g_h);
    cudaGetSymbolAddress((void**)&pqkv,  g_qkv);
    cudaGetSymbolAddress((void**)&pff,   g_ff);
    cudaGetSymbolAddress((void**)&pctx,  g_ctx);
    cudaGetSymbolAddress((void**)&pK,    g_K);
    cudaGetSymbolAddress((void**)&pV,    g_V);
    cudaGetSymbolAddress((void**)&pxv,   g_xvec);
    cudaGetSymbolAddress((void**)&pqv,   g_qvec);
    cudaGetSymbolAddress((void**)&pfv,   g_fvec);
    cudaGetSymbolAddress((void**)&pgv,   g_gvec);
    cudaGetSymbolAddress((void**)&ppart, g_part);
    cudaGetSymbolAddress((void**)&pattA, g_attA);
    cudaGetSymbolAddress((void**)&pattM, g_attM);
    cudaGetSymbolAddress((void**)&pattL, g_attL);

    const int MB = (M0 + TM - 1) / TM;  // 17

    // ---- embed ----
    {
        int n = B * S0 * D;
        embed_kernel<<<(n + 255) / 256, 256>>>(feats, img_pos, intent, int_emb,
                                               past, past_W, past_b, time_emb, px);
    }

    // ---- prefill: 3 layers ----
    for (int l = 0; l < L; l++) {
        float* KcL = pK + (size_t)l * CACHE_L;
        float* VcL = pV + (size_t)l * CACHE_L;

        ln_kernel<<<M0, 256>>>(px, ph, ln1_g + l * D, ln1_b + l * D);
        gemm_kernel<<<dim3(D3 / TN, MB), 256>>>(
            ph, qkv_W + (size_t)l * D * D3, qkv_b + l * D3, nullptr, pqkv, M0, D3, D, 0);
        {
            int n = B * S0 * D;
            scatter_kv<<<(n + 255) / 256, 256>>>(pqkv, KcL, VcL);
        }
        attn_prefill<<<dim3((S0 + 3) / 4, B * H), 128>>>(pqkv, KcL, VcL, pctx);
        gemm_kernel<<<dim3(D / TN, MB), 256>>>(
            pctx, out_W + (size_t)l * D * D, out_b + l * D, px, px, M0, D, D, 0);
        ln_kernel<<<M0, 256>>>(px, ph, ln2_g + l * D, ln2_b + l * D);
        gemm_kernel<<<dim3(DFF / TN, MB), 256>>>(
            ph, ff1_W + (size_t)l * D * DFF, ff1_b + l * DFF, nullptr, pff, M0, DFF, D, 1);
        gemm_kernel<<<dim3(D / TN, MB), 256>>>(
            pff, ff2_W + (size_t)l * DFF * D, ff2_b + l * D, px, px, M0, D, DFF, 0);
    }

    copy_last<<<(B * D + 255) / 256, 256>>>(px, pxv);

    // ---- autoregressive decode: 20 steps ----
    for (int t = 0; t < T_DEC; t++) {
        // head: gvec = gelu(xvec @ dec1 + b)
        gemv_part<<<dim3(D / 256, 8), 256>>>(pxv, dec1_W, ppart, D, D, 8, AP_PLAIN,
                                             nullptr, nullptr, nullptr, nullptr, nullptr);
        gemv_fin<<<D / 256, 256>>>(ppart, dec1_b, nullptr, pgv, D, 8, 2, 0, 0,
                                   nullptr, nullptr, nullptr);
        head2_kernel<<<B, 256>>>(pgv, dec2_W, dec2_b, pos_W, pos_b, time_emb, t, out, pxv);

        int s_new = S0 + t;
        for (int l = 0; l < L; l++) {
            float* KcL = pK + (size_t)l * CACHE_L;
            float* VcL = pV + (size_t)l * CACHE_L;

            // qkv = LN1(xvec) @ qkv_W + b   (scatter k,v into cache; q -> qvec)
            gemv_part<<<dim3(D3 / 256, 8), 256>>>(pxv, qkv_W + (size_t)l * D * D3, ppart,
                                                  D3, D, 8, AP_LN,
                                                  ln1_g + l * D, ln1_b + l * D,
                                                  nullptr, nullptr, nullptr);
            gemv_fin<<<D3 / 256, 256>>>(ppart, qkv_b + l * D3, nullptr, nullptr,
                                        D3, 8, 0, 1, s_new, KcL, VcL, pqv);
            // attention (split-j flash partials)
            attn_dec<<<dim3(B * H, NSPLIT), 256>>>(pqv, KcL, VcL, s_new + 1,
                                                   pattA, pattM, pattL);
            // out projection (combine fused in A-prep), residual into xvec
            gemv_part<<<dim3(D / 256, 8), 256>>>(nullptr, out_W + (size_t)l * D * D, ppart,
                                                 D, D, 8, AP_ATT, nullptr, nullptr,
                                                 pattA, pattM, pattL);
            gemv_fin<<<D / 256, 256>>>(ppart, out_b + l * D, pxv, pxv, D, 8, 0, 0, 0,
                                       nullptr, nullptr, nullptr);
            // ff1 = relu(LN2(xvec) @ ff1_W + b)
            gemv_part<<<dim3(DFF / 256, 8), 256>>>(pxv, ff1_W + (size_t)l * D * DFF, ppart,
                                                   DFF, D, 8, AP_LN,
                                                   ln2_g + l * D, ln2_b + l * D,
                                                   nullptr, nullptr, nullptr);
            gemv_fin<<<DFF / 256, 256>>>(ppart, ff1_b + l * DFF, nullptr, pfv,
                                         DFF, 8, 1, 0, 0, nullptr, nullptr, nullptr);
            // ff2, residual into xvec
            gemv_part<<<dim3(D / 256, 16), 256>>>(pfv, ff2_W + (size_t)l * DFF * D, ppart,
                                                  D, DFF, 16, AP_PLAIN,
                                                  nullptr, nullptr, nullptr, nullptr, nullptr);
            gemv_fin<<<D / 256, 256>>>(ppart, ff2_b + l * D, pxv, pxv, D, 16, 0, 0, 0,
                                       nullptr, nullptr, nullptr);
        }
    }
}

// round 9
// speedup vs baseline: 7.1791x; 1.0292x over previous
#include <cuda_runtime.h>
#include <math.h>

#define B 2
#define D 768
#define H 16
#define HD 48
#define L 3
#define N_IMG 1024
#define N_PAST 16
#define T_DEC 20
#define S0 (N_IMG + 1 + N_PAST)    // 1041
#define SMAX (S0 + T_DEC)          // 1061
#define M0 (B * S0)                // 2082
#define D3 (3 * D)                 // 2304
#define DFF (4 * D)                // 3072
#define CACHE_L (B * H * SMAX * HD)
#define NSPLIT 4

#define ATT_SCALE 0.14433756729740643f  // 1/sqrt(48)

// ------------------------- static device scratch -------------------------
__device__ float g_x[M0 * D];
__device__ float g_h[M0 * D];
__device__ float g_qkv[M0 * D3];
__device__ float g_ff[M0 * DFF];
__device__ float g_ctx[M0 * D];
__device__ float g_K[L * CACHE_L];
__device__ float g_V[L * CACHE_L];
__device__ float g_xvec[B * D];
__device__ float g_qvec[B * D];
__device__ float g_fvec[B * DFF];
__device__ float g_gvec[B * D];
__device__ float g_part[8 * 2 * DFF];          // split-K partials
__device__ float g_attA[B * H * NSPLIT * HD];
__device__ float g_attM[B * H * NSPLIT];
__device__ float g_attL[B * H * NSPLIT];

__device__ __forceinline__ float gelu_exact(float x) {
    return 0.5f * x * (1.0f + erff(x * 0.7071067811865475f));
}

// ------------------------- embed -------------------------
__global__ void embed_kernel(const float* __restrict__ feats,
                             const float* __restrict__ img_pos,
                             const int* __restrict__ intent,
                             const float* __restrict__ int_emb,
                             const float* __restrict__ past,
                             const float* __restrict__ past_W,
                             const float* __restrict__ past_b,
                             const float* __restrict__ time_emb,
                             float* __restrict__ X) {
    int idx = blockIdx.x * blockDim.x + threadIdx.x;
    if (idx >= B * S0 * D) return;
    int d = idx % D;
    int s = (idx / D) % S0;
    int b = idx / (D * S0);
    float v;
    if (s < N_IMG) {
        v = feats[((size_t)b * D + d) * N_IMG + s] + img_pos[(size_t)s * D + d];
    } else if (s == N_IMG) {
        int ii = intent[b] - 1;
        ii = ii < 0 ? 0 : (ii > 2 ? 2 : ii);
        v = int_emb[ii * D + d];
    } else {
        int j = s - N_IMG - 1;
        v = past_b[d] + time_emb[j * D + d];
        #pragma unroll
        for (int c = 0; c < 6; c++)
            v += past[(b * N_PAST + j) * 6 + c] * past_W[c * D + d];
    }
    X[idx] = v;
}

// ------------------------- layernorm (prefill; one block per row) -------------------------
__global__ void ln_kernel(const float* __restrict__ X, float* __restrict__ Y,
                          const float* __restrict__ gam, const float* __restrict__ bet) {
    int row = blockIdx.x;
    const float* x = X + (size_t)row * D;
    float* y = Y + (size_t)row * D;
    __shared__ float red[256];
    int t = threadIdx.x;
    float s = 0.f;
    for (int i = t; i < D; i += 256) s += x[i];
    red[t] = s; __syncthreads();
    for (int o = 128; o > 0; o >>= 1) { if (t < o) red[t] += red[t + o]; __syncthreads(); }
    float mean = red[0] * (1.0f / D);
    __syncthreads();
    float vs = 0.f;
    for (int i = t; i < D; i += 256) { float dd = x[i] - mean; vs += dd * dd; }
    red[t] = vs; __syncthreads();
    for (int o = 128; o > 0; o >>= 1) { if (t < o) red[t] += red[t + o]; __syncthreads(); }
    float inv = rsqrtf(red[0] * (1.0f / D) + 1e-5f);
    for (int i = t; i < D; i += 256)
        y[i] = (x[i] - mean) * inv * gam[i] + bet[i];
}

// ------------------------- 128x128x16 fp32 GEMM, DOUBLE BUFFERED -------------------------
#define TM 128
#define TN 128
#define TK 16
__global__ void __launch_bounds__(256, 2)
gemm_kernel(const float* __restrict__ A, const float* __restrict__ W,
            const float* __restrict__ bias, const float* __restrict__ R,
            float* __restrict__ C, int M, int N, int K, int act) {
    __shared__ float As[2][TK][TM];
    __shared__ float Ws[2][TK][TN];
    int tid = threadIdx.x;
    int warp = tid >> 5, lane = tid & 31;
    int wm = warp & 1, wn = warp >> 1;
    int lm = lane & 7, ln = lane >> 3;
    int tr = (wm * 8 + lm) * 8;
    int tc = (wn * 4 + ln) * 8;
    int row0 = blockIdx.y * TM, col0 = blockIdx.x * TN;
    float acc[8][8] = {};

    const int nt = K / TK;   // K is always a multiple of 16 here

    // preload tile 0 into buffer 0
    {
        #pragma unroll
        for (int i = 0; i < 2; i++) {
            int idx = tid * 2 + i;
            int r = idx >> 2, c4 = idx & 3;
            int gm = row0 + r;
            float4 v = make_float4(0.f, 0.f, 0.f, 0.f);
            if (gm < M) v = *reinterpret_cast<const float4*>(&A[(size_t)gm * K + c4 * 4]);
            As[0][c4 * 4 + 0][r] = v.x;
            As[0][c4 * 4 + 1][r] = v.y;
            As[0][c4 * 4 + 2][r] = v.z;
            As[0][c4 * 4 + 3][r] = v.w;
        }
        #pragma unroll
        for (int i = 0; i < 2; i++) {
            int idx = tid * 2 + i;
            int kk = idx >> 5, c4 = idx & 31;
            *reinterpret_cast<float4*>(&Ws[0][kk][c4 * 4]) =
                *reinterpret_cast<const float4*>(&W[(size_t)kk * N + col0 + c4 * 4]);
        }
    }
    __syncthreads();

    for (int it = 0; it < nt; it++) {
        int buf = it & 1;
        int nxt = buf ^ 1;
        // issue next tile's loads before compute (overlap with FMAs)
        if (it + 1 < nt) {
            int k0 = (it + 1) * TK;
            #pragma unroll
            for (int i = 0; i < 2; i++) {
                int idx = tid * 2 + i;
                int r = idx >> 2, c4 = idx & 3;
                int gm = row0 + r;
                float4 v = make_float4(0.f, 0.f, 0.f, 0.f);
                if (gm < M) v = *reinterpret_cast<const float4*>(&A[(size_t)gm * K + k0 + c4 * 4]);
                As[nxt][c4 * 4 + 0][r] = v.x;
                As[nxt][c4 * 4 + 1][r] = v.y;
                As[nxt][c4 * 4 + 2][r] = v.z;
                As[nxt][c4 * 4 + 3][r] = v.w;
            }
            #pragma unroll
            for (int i = 0; i < 2; i++) {
                int idx = tid * 2 + i;
                int kk = idx >> 5, c4 = idx & 31;
                *reinterpret_cast<float4*>(&Ws[nxt][kk][c4 * 4]) =
                    *reinterpret_cast<const float4*>(&W[(size_t)(k0 + kk) * N + col0 + c4 * 4]);
            }
        }
        #pragma unroll
        for (int kk = 0; kk < TK; kk++) {
            float a[8], w[8];
            *reinterpret_cast<float4*>(a)     = *reinterpret_cast<const float4*>(&As[buf][kk][tr]);
            *reinterpret_cast<float4*>(a + 4) = *reinterpret_cast<const float4*>(&As[buf][kk][tr + 4]);
            *reinterpret_cast<float4*>(w)     = *reinterpret_cast<const float4*>(&Ws[buf][kk][tc]);
            *reinterpret_cast<float4*>(w + 4) = *reinterpret_cast<const float4*>(&Ws[buf][kk][tc + 4]);
            #pragma unroll
            for (int i = 0; i < 8; i++)
                #pragma unroll
                for (int j = 0; j < 8; j++)
                    acc[i][j] += a[i] * w[j];
        }
        __syncthreads();
    }

    #pragma unroll
    for (int i = 0; i < 8; i++) {
        int gm = row0 + tr + i;
        if (gm >= M) continue;
        #pragma unroll
        for (int jc = 0; jc < 2; jc++) {
            int gn = col0 + tc + jc * 4;
            float4 bv = *reinterpret_cast<const float4*>(&bias[gn]);
            float4 v;
            v.x = acc[i][jc * 4 + 0] + bv.x;
            v.y = acc[i][jc * 4 + 1] + bv.y;
            v.z = acc[i][jc * 4 + 2] + bv.z;
            v.w = acc[i][jc * 4 + 3] + bv.w;
            if (R) {
                float4 rv = *reinterpret_cast<const float4*>(&R[(size_t)gm * N + gn]);
                v.x += rv.x; v.y += rv.y; v.z += rv.z; v.w += rv.w;
            }
            if (act == 1) {
                v.x = fmaxf(v.x, 0.f); v.y = fmaxf(v.y, 0.f);
                v.z = fmaxf(v.z, 0.f); v.w = fmaxf(v.w, 0.f);
            }
            *reinterpret_cast<float4*>(&C[(size_t)gm * N + gn]) = v;
        }
    }
}

// ------------------------- scatter prefill K,V to caches -------------------------
__global__ void scatter_kv(const float* __restrict__ qkv,
                           float* __restrict__ Kc, float* __restrict__ Vc) {
    int idx = blockIdx.x * blockDim.x + threadIdx.x;
    if (idx >= B * S0 * D) return;
    int e = idx % D;
    int s = (idx / D) % S0;
    int b = idx / (D * S0);
    int h = e / HD, ee = e % HD;
    size_t dst = (((size_t)(b * H + h)) * SMAX + s) * HD + ee;
    size_t src = ((size_t)(b * S0 + s)) * D3;
    Kc[dst] = qkv[src + D + e];
    Vc[dst] = qkv[src + 2 * D + e];
}

// ------------------------- prefill attention (flash, warp per query) -------------------------
__global__ void attn_prefill(const float* __restrict__ QKV,
                             const float* __restrict__ Kc,
                             const float* __restrict__ Vc,
                             float* __restrict__ O) {
    int bh = blockIdx.y;
    int b = bh / H, h = bh % H;
    int q0 = blockIdx.x * 4;
    int warp = threadIdx.x >> 5, lane = threadIdx.x & 31;
    int qrow = q0 + warp;
    if (qrow >= S0) qrow = S0 - 1;

    __shared__ float qs[4][HD];
    __shared__ float Ks[32][49];
    __shared__ float Vs[32][49];

    {
        size_t qb = ((size_t)(b * S0 + qrow)) * D3 + h * HD;
        qs[warp][lane] = QKV[qb + lane];
        if (lane < 16) qs[warp][32 + lane] = QKV[qb + 32 + lane];
    }
    __syncthreads();

    int jmax_blk = q0 + 3; if (jmax_blk >= S0) jmax_blk = S0 - 1;
    size_t kvbase = (size_t)bh * SMAX * HD;

    float mrun = -INFINITY, srun = 0.f, acc0 = 0.f, acc1 = 0.f;

    for (int j0 = 0; j0 <= jmax_blk; j0 += 32) {
        for (int i = threadIdx.x; i < 32 * HD; i += 128) {
            int r = i / HD, c = i % HD;
            int j = j0 + r;
            float kv = 0.f, vv = 0.f;
            if (j < S0) {
                kv = Kc[kvbase + (size_t)j * HD + c];
                vv = Vc[kvbase + (size_t)j * HD + c];
            }
            Ks[r][c] = kv; Vs[r][c] = vv;
        }
        __syncthreads();

        int j = j0 + lane;
        float s = -INFINITY;
        if (j <= qrow) {
            s = 0.f;
            #pragma unroll
            for (int d = 0; d < HD; d++) s += qs[warp][d] * Ks[lane][d];
            s *= ATT_SCALE;
        }
        float cm = s;
        #pragma unroll
        for (int o = 16; o > 0; o >>= 1) cm = fmaxf(cm, __shfl_xor_sync(0xffffffffu, cm, o));
        float mnew = fmaxf(mrun, cm);
        float corr = expf(mrun - mnew);
        float p = (j <= qrow) ? expf(s - mnew) : 0.f;
        float ps = p;
        #pragma unroll
        for (int o = 16; o > 0; o >>= 1) ps += __shfl_xor_sync(0xffffffffu, ps, o);
        srun = srun * corr + ps;
        mrun = mnew;
        acc0 *= corr; acc1 *= corr;
        #pragma unroll 4
        for (int src = 0; src < 32; src++) {
            float pp = __shfl_sync(0xffffffffu, p, src);
            acc0 += pp * Vs[src][lane];
            if (lane < 16) acc1 += pp * Vs[src][32 + lane];
        }
        __syncthreads();
    }

    if (q0 + warp < S0) {
        float inv = 1.f / srun;
        size_t ob = ((size_t)(b * S0 + qrow)) * D + h * HD;
        O[ob + lane] = acc0 * inv;
        if (lane < 16) O[ob + 32 + lane] = acc1 * inv;
    }
}

// ------------------------- copy last prefill row -------------------------
__global__ void copy_last(const float* __restrict__ X, float* __restrict__ xv) {
    int idx = blockIdx.x * blockDim.x + threadIdx.x;
    if (idx >= B * D) return;
    int b = idx / D, d = idx % D;
    xv[idx] = X[((size_t)(b * S0 + S0 - 1)) * D + d];
}

// ===================== decode: split-K GEMV, two stage (R2-proven) =====================
#define AP_PLAIN 0
#define AP_LN    1
#define AP_ATT   2

__global__ void __launch_bounds__(256)
gemv_part(const float* __restrict__ Avec, const float* __restrict__ W,
          float* __restrict__ part, int N, int K, int KS, int mode,
          const float* __restrict__ gam, const float* __restrict__ bet,
          const float* __restrict__ attA, const float* __restrict__ attM,
          const float* __restrict__ attL) {
    __shared__ float Asl[2][192];
    __shared__ float red[256], red2[256];
    int t = threadIdx.x;
    int len = K / KS;
    int k0 = blockIdx.y * len;

    if (mode == AP_PLAIN) {
        for (int i = t; i < 2 * len; i += 256) {
            int m = i / len, kk = i % len;
            Asl[m][kk] = Avec[m * K + k0 + kk];
        }
    } else if (mode == AP_LN) {
        float mean[2], inv[2];
        #pragma unroll
        for (int m = 0; m < 2; m++) {
            float s = 0.f, ss = 0.f;
            for (int i = t; i < K; i += 256) {
                float v = Avec[m * K + i];
                s += v; ss += v * v;
            }
            red[t] = s; red2[t] = ss; __syncthreads();
            for (int o = 128; o > 0; o >>= 1) {
                if (t < o) { red[t] += red[t + o]; red2[t] += red2[t + o]; }
                __syncthreads();
            }
            mean[m] = red[0] * (1.0f / D);
            inv[m] = rsqrtf(red2[0] * (1.0f / D) - mean[m] * mean[m] + 1e-5f);
            __syncthreads();
        }
        for (int i = t; i < 2 * len; i += 256) {
            int m = i / len, kk = i % len;
            int gk = k0 + kk;
            Asl[m][kk] = (Avec[m * K + gk] - mean[m]) * inv[m] * gam[gk] + bet[gk];
        }
    } else { // AP_ATT: combine NSPLIT flash partials
        for (int i = t; i < 2 * len; i += 256) {
            int m = i / len, e = k0 + i % len;
            int h = e / HD, d = e % HD;
            int bh = m * H + h;
            float M = -INFINITY;
            #pragma unroll
            for (int s = 0; s < NSPLIT; s++) M = fmaxf(M, attM[bh * NSPLIT + s]);
            float num = 0.f, den = 0.f;
            #pragma unroll
            for (int s = 0; s < NSPLIT; s++) {
                float w = expf(attM[bh * NSPLIT + s] - M);
                num += w * attA[(bh * NSPLIT + s) * HD + d];
                den += w * attL[bh * NSPLIT + s];
            }
            Asl[m][i % len] = num / den;
        }
    }
    __syncthreads();

    int n = blockIdx.x * 256 + t;
    const float* Wp = W + (size_t)k0 * N + n;
    float a0 = 0.f, a1 = 0.f;
    #pragma unroll 8
    for (int kk = 0; kk < len; kk++) {
        float w = *Wp; Wp += N;
        a0 += Asl[0][kk] * w;
        a1 += Asl[1][kk] * w;
    }
    part[(blockIdx.y * 2 + 0) * N + n] = a0;
    part[(blockIdx.y * 2 + 1) * N + n] = a1;
}

__global__ void __launch_bounds__(256)
gemv_fin(const float* __restrict__ part, const float* __restrict__ bias,
         const float* __restrict__ Res, float* __restrict__ dst,
         int N, int KS, int act, int scatter, int s_new,
         float* __restrict__ Kc, float* __restrict__ Vc, float* __restrict__ qv) {
    int n = blockIdx.x * 256 + threadIdx.x;
    float a0 = bias[n], a1 = a0;
    for (int ks = 0; ks < KS; ks++) {
        a0 += part[(ks * 2 + 0) * N + n];
        a1 += part[(ks * 2 + 1) * N + n];
    }
    if (Res) { a0 += Res[n]; a1 += Res[N + n]; }
    if (act == 1) { a0 = fmaxf(a0, 0.f); a1 = fmaxf(a1, 0.f); }
    else if (act == 2) { a0 = gelu_exact(a0); a1 = gelu_exact(a1); }
    if (scatter == 0) {
        dst[n] = a0; dst[N + n] = a1;
    } else {
        if (n < D) {
            qv[n] = a0; qv[D + n] = a1;
        } else if (n < 2 * D) {
            int e = n - D; int h = e / HD, ee = e % HD;
            Kc[(((size_t)h) * SMAX + s_new) * HD + ee] = a0;
            Kc[(((size_t)(H + h)) * SMAX + s_new) * HD + ee] = a1;
        } else {
            int e = n - 2 * D; int h = e / HD, ee = e % HD;
            Vc[(((size_t)h) * SMAX + s_new) * HD + ee] = a0;
            Vc[(((size_t)(H + h)) * SMAX + s_new) * HD + ee] = a1;
        }
    }
}

// ------------------------- decode attention, split over j -------------------------
__global__ void __launch_bounds__(256)
attn_dec(const float* __restrict__ qv, const float* __restrict__ Kc,
         const float* __restrict__ Vc, int Slen,
         float* __restrict__ attA, float* __restrict__ attM, float* __restrict__ attL) {
    int bh = blockIdx.x;
    int split = blockIdx.y;
    int b = bh / H, h = bh % H;
    int len = (Slen + NSPLIT - 1) / NSPLIT;
    int j0 = split * len;
    int j1 = min(j0 + len, Slen);
    int cnt = j1 - j0;

    __shared__ float qs[HD];
    __shared__ float sc[272];
    __shared__ float red[256];
    __shared__ float red2[5 * HD];
    int t = threadIdx.x;
    if (t < HD) qs[t] = qv[b * D + h * HD + t];
    __syncthreads();

    size_t base = (size_t)bh * SMAX * HD;
    float lmax = -INFINITY;
    for (int jl = t; jl < cnt; jl += 256) {
        const float* kp = Kc + base + (size_t)(j0 + jl) * HD;
        float s = 0.f;
        #pragma unroll
        for (int d = 0; d < HD; d++) s += qs[d] * kp[d];
        s *= ATT_SCALE;
        sc[jl] = s;
        lmax = fmaxf(lmax, s);
    }
    red[t] = lmax; __syncthreads();
    for (int o = 128; o > 0; o >>= 1) { if (t < o) red[t] = fmaxf(red[t], red[t + o]); __syncthreads(); }
    float m = red[0];
    __syncthreads();
    float ls = 0.f;
    for (int jl = t; jl < cnt; jl += 256) {
        float p = expf(sc[jl] - m);
        sc[jl] = p;
        ls += p;
    }
    red[t] = ls; __syncthreads();
    for (int o = 128; o > 0; o >>= 1) { if (t < o) red[t] += red[t + o]; __syncthreads(); }
    float l = red[0];
    __syncthreads();

    if (t < 5 * HD) {
        int d = t % HD, g = t / HD;
        float a = 0.f;
        for (int jl = g; jl < cnt; jl += 5)
            a += sc[jl] * Vc[base + (size_t)(j0 + jl) * HD + d];
        red2[g * HD + d] = a;
    }
    __syncthreads();
    if (t < HD) {
        float a = red2[t] + red2[HD + t] + red2[2 * HD + t] + red2[3 * HD + t] + red2[4 * HD + t];
        attA[(bh * NSPLIT + split) * HD + t] = a;
        if (t == 0) { attM[bh * NSPLIT + split] = m; attL[bh * NSPLIT + split] = l; }
    }
}

// ------------------------- decode head stage 2 + next-token embed -------------------------
__global__ void head2_kernel(const float* __restrict__ gvec,
                             const float* __restrict__ dec2_W, const float* __restrict__ dec2_b,
                             const float* __restrict__ pos_W, const float* __restrict__ pos_b,
                             const float* __restrict__ time_emb, int t_step,
                             float* __restrict__ out, float* __restrict__ xv) {
    int b = blockIdx.x;
    __shared__ float r0[256], r1[256];
    int tid = threadIdx.x;
    float p0 = 0.f, p1 = 0.f;
    for (int k = tid; k < D; k += 256) {
        float g = gvec[b * D + k];
        p0 += g * dec2_W[k * 2];
        p1 += g * dec2_W[k * 2 + 1];
    }
    r0[tid] = p0; r1[tid] = p1; __syncthreads();
    for (int o = 128; o > 0; o >>= 1) {
        if (tid < o) { r0[tid] += r0[tid + o]; r1[tid] += r1[tid + o]; }
        __syncthreads();
    }
    p0 = r0[0] + dec2_b[0];
    p1 = r1[0] + dec2_b[1];
    if (tid == 0) {
        out[(b * T_DEC + t_step) * 2]     = p0;
        out[(b * T_DEC + t_step) * 2 + 1] = p1;
    }
    for (int d = tid; d < D; d += 256)
        xv[b * D + d] = p0 * pos_W[d] + p1 * pos_W[D + d] + pos_b[d]
                        + time_emb[(N_PAST + t_step) * D + d];
}

// ------------------------- host orchestration -------------------------
extern "C" void kernel_launch(void* const* d_in, const int* in_sizes, int n_in,
                              void* d_out, int out_size) {
    const float* feats    = (const float*)d_in[0];
    const float* past     = (const float*)d_in[1];
    const int*   intent   = (const int*)  d_in[2];
    const float* img_pos  = (const float*)d_in[3];
    const float* time_emb = (const float*)d_in[4];
    const float* int_emb  = (const float*)d_in[5];
    const float* past_W   = (const float*)d_in[6];
    const float* past_b   = (const float*)d_in[7];
    const float* pos_W    = (const float*)d_in[8];
    const float* pos_b    = (const float*)d_in[9];
    const float* ln1_g    = (const float*)d_in[10];
    const float* ln1_b    = (const float*)d_in[11];
    const float* qkv_W    = (const float*)d_in[12];
    const float* qkv_b    = (const float*)d_in[13];
    const float* out_W    = (const float*)d_in[14];
    const float* out_b    = (const float*)d_in[15];
    const float* ln2_g    = (const float*)d_in[16];
    const float* ln2_b    = (const float*)d_in[17];
    const float* ff1_W    = (const float*)d_in[18];
    const float* ff1_b    = (const float*)d_in[19];
    const float* ff2_W    = (const float*)d_in[20];
    const float* ff2_b    = (const float*)d_in[21];
    const float* dec1_W   = (const float*)d_in[22];
    const float* dec1_b   = (const float*)d_in[23];
    const float* dec2_W   = (const float*)d_in[24];
    const float* dec2_b   = (const float*)d_in[25];
    float* out = (float*)d_out;

    float *px, *ph, *pqkv, *pff, *pctx, *pK, *pV, *pxv, *pqv, *pfv, *pgv;
    float *ppart, *pattA, *pattM, *pattL;
    cudaGetSymbolAddress((void**)&px,    g_x);
    cudaGetSymbolAddress((void**)&ph,    g_h);
    cudaGetSymbolAddress((void**)&pqkv,  g_qkv);
    cudaGetSymbolAddress((void**)&pff,   g_ff);
    cudaGetSymbolAddress((void**)&pctx,  g_ctx);
    cudaGetSymbolAddress((void**)&pK,    g_K);
    cudaGetSymbolAddress((void**)&pV,    g_V);
    cudaGetSymbolAddress((void**)&pxv,   g_xvec);
    cudaGetSymbolAddress((void**)&pqv,   g_qvec);
    cudaGetSymbolAddress((void**)&pfv,   g_fvec);
    cudaGetSymbolAddress((void**)&pgv,   g_gvec);
    cudaGetSymbolAddress((void**)&ppart, g_part);
    cudaGetSymbolAddress((void**)&pattA, g_attA);
    cudaGetSymbolAddress((void**)&pattM, g_attM);
    cudaGetSymbolAddress((void**)&pattL, g_attL);

    const int MB = (M0 + TM - 1) / TM;  // 17

    // ---- embed ----
    {
        int n = B * S0 * D;
        embed_kernel<<<(n + 255) / 256, 256>>>(feats, img_pos, intent, int_emb,
                                               past, past_W, past_b, time_emb, px);
    }

    // ---- prefill: 3 layers ----
    for (int l = 0; l < L; l++) {
        float* KcL = pK + (size_t)l * CACHE_L;
        float* VcL = pV + (size_t)l * CACHE_L;

        ln_kernel<<<M0, 256>>>(px, ph, ln1_g + l * D, ln1_b + l * D);
        gemm_kernel<<<dim3(D3 / TN, MB), 256>>>(
            ph, qkv_W + (size_t)l * D * D3, qkv_b + l * D3, nullptr, pqkv, M0, D3, D, 0);
        {
            int n = B * S0 * D;
            scatter_kv<<<(n + 255) / 256, 256>>>(pqkv, KcL, VcL);
        }
        attn_prefill<<<dim3((S0 + 3) / 4, B * H), 128>>>(pqkv, KcL, VcL, pctx);
        gemm_kernel<<<dim3(D / TN, MB), 256>>>(
            pctx, out_W + (size_t)l * D * D, out_b + l * D, px, px, M0, D, D, 0);
        ln_kernel<<<M0, 256>>>(px, ph, ln2_g + l * D, ln2_b + l * D);
        gemm_kernel<<<dim3(DFF / TN, MB), 256>>>(
            ph, ff1_W + (size_t)l * D * DFF, ff1_b + l * DFF, nullptr, pff, M0, DFF, D, 1);
        gemm_kernel<<<dim3(D / TN, MB), 256>>>(
            pff, ff2_W + (size_t)l * DFF * D, ff2_b + l * D, px, px, M0, D, DFF, 0);
    }

    copy_last<<<(B * D + 255) / 256, 256>>>(px, pxv);

    // ---- autoregressive decode: 20 steps (R2-proven two-stage path) ----
    for (int t = 0; t < T_DEC; t++) {
        // head: gvec = gelu(xvec @ dec1 + b)
        gemv_part<<<dim3(D / 256, 8), 256>>>(pxv, dec1_W, ppart, D, D, 8, AP_PLAIN,
                                             nullptr, nullptr, nullptr, nullptr, nullptr);
        gemv_fin<<<D / 256, 256>>>(ppart, dec1_b, nullptr, pgv, D, 8, 2, 0, 0,
                                   nullptr, nullptr, nullptr);
        head2_kernel<<<B, 256>>>(pgv, dec2_W, dec2_b, pos_W, pos_b, time_emb, t, out, pxv);

        if (t == T_DEC - 1) break;   // final encoder pass is never consumed

        int s_new = S0 + t;
        for (int l = 0; l < L; l++) {
            float* KcL = pK + (size_t)l * CACHE_L;
            float* VcL = pV + (size_t)l * CACHE_L;

            gemv_part<<<dim3(D3 / 256, 8), 256>>>(pxv, qkv_W + (size_t)l * D * D3, ppart,
                                                  D3, D, 8, AP_LN,
                                                  ln1_g + l * D, ln1_b + l * D,
                                                  nullptr, nullptr, nullptr);
            gemv_fin<<<D3 / 256, 256>>>(ppart, qkv_b + l * D3, nullptr, nullptr,
                                        D3, 8, 0, 1, s_new, KcL, VcL, pqv);
            attn_dec<<<dim3(B * H, NSPLIT), 256>>>(pqv, KcL, VcL, s_new + 1,
                                                   pattA, pattM, pattL);
            gemv_part<<<dim3(D / 256, 8), 256>>>(nullptr, out_W + (size_t)l * D * D, ppart,
                                                 D, D, 8, AP_ATT, nullptr, nullptr,
                                                 pattA, pattM, pattL);
            gemv_fin<<<D / 256, 256>>>(ppart, out_b + l * D, pxv, pxv, D, 8, 0, 0, 0,
                                       nullptr, nullptr, nullptr);
            gemv_part<<<dim3(DFF / 256, 8), 256>>>(pxv, ff1_W + (size_t)l * D * DFF, ppart,
                                                   DFF, D, 8, AP_LN,
                                                   ln2_g + l * D, ln2_b + l * D,
                                                   nullptr, nullptr, nullptr);
            gemv_fin<<<DFF / 256, 256>>>(ppart, ff1_b + l * DFF, nullptr, pfv,
                                         DFF, 8, 1, 0, 0, nullptr, nullptr, nullptr);
            gemv_part<<<dim3(D / 256, 16), 256>>>(pfv, ff2_W + (size_t)l * DFF * D, ppart,
                                                  D, DFF, 16, AP_PLAIN,
                                                  nullptr, nullptr, nullptr, nullptr, nullptr);
            gemv_fin<<<D / 256, 256>>>(ppart, ff2_b + l * D, pxv, pxv, D, 16, 0, 0, 0,
                                       nullptr, nullptr, nullptr);
        }
    }
}